// round 1
// baseline (speedup 1.0000x reference)
#include <cuda_runtime.h>
#include <math.h>
#include <stddef.h>

// ---------------------------------------------------------------------------
// Problem dims (fixed by the dataset)
// ---------------------------------------------------------------------------
#define BATCH 4
#define T 1024
#define H 1024
#define NH 16
#define HD 64
#define CD 768
#define SC 77          // cross-attention context length
#define FF 4096
#define BT (BATCH * T) // 4096 token rows

// ---------------------------------------------------------------------------
// Scratch (static device globals; no runtime allocation allowed)
// ---------------------------------------------------------------------------
__device__ float g_x[BT * H];     // running residual stream
__device__ float g_ln[BT * H];    // layernorm output
__device__ float g_q[BT * H];
__device__ float g_k[BT * H];
__device__ float g_v[BT * H];
__device__ float g_attn[BT * H];  // attention output (pre-projection)
__device__ float g_h[BT * FF];    // FFN hidden

// ---------------------------------------------------------------------------
// Utility reductions
// ---------------------------------------------------------------------------
__device__ __forceinline__ float warpMax(float v) {
#pragma unroll
    for (int o = 16; o; o >>= 1) v = fmaxf(v, __shfl_xor_sync(0xffffffffu, v, o));
    return v;
}
__device__ __forceinline__ float warpSum(float v) {
#pragma unroll
    for (int o = 16; o; o >>= 1) v += __shfl_xor_sync(0xffffffffu, v, o);
    return v;
}

// ---------------------------------------------------------------------------
// Copy kernel (seed residual stream)
// ---------------------------------------------------------------------------
__global__ void copy_kernel(const float* __restrict__ in, float* __restrict__ out, int n) {
    int i = blockIdx.x * blockDim.x + threadIdx.x;
    if (i < n) out[i] = in[i];
}

// ---------------------------------------------------------------------------
// LayerNorm: one block per row of H=1024
// ---------------------------------------------------------------------------
__global__ void ln_kernel(const float* __restrict__ in,
                          const float* __restrict__ gamma,
                          const float* __restrict__ beta,
                          float* __restrict__ out) {
    int row = blockIdx.x;
    const float* r = in + (size_t)row * H;
    int tid = threadIdx.x;

    float s = 0.f, s2 = 0.f;
    for (int i = tid; i < H; i += 256) {
        float v = r[i];
        s += v; s2 += v * v;
    }
    __shared__ float sh_s[8], sh_s2[8];
    float ws = warpSum(s), ws2 = warpSum(s2);
    int wid = tid >> 5, lane = tid & 31;
    if (lane == 0) { sh_s[wid] = ws; sh_s2[wid] = ws2; }
    __syncthreads();
    float tot = 0.f, tot2 = 0.f;
#pragma unroll
    for (int w = 0; w < 8; w++) { tot += sh_s[w]; tot2 += sh_s2[w]; }
    float mean = tot * (1.0f / H);
    float var = tot2 * (1.0f / H) - mean * mean;
    float inv = rsqrtf(var + 1e-5f);

    float* o = out + (size_t)row * H;
    for (int i = tid; i < H; i += 256) {
        o[i] = (r[i] - mean) * inv * gamma[i] + beta[i];
    }
}

// ---------------------------------------------------------------------------
// FP32 tiled GEMM:  C[M,N] = A[M,K] @ W[K,N] (+bias) (+GELU) (+residual)
//   BM=128, BN=128, BK=8, 256 threads, 8x8 microtile per thread.
//   K must be a multiple of 8, N a multiple of 128; M guarded.
// ---------------------------------------------------------------------------
#define BM 128
#define BN 128
#define BKK 8

__global__ __launch_bounds__(256, 2)
void gemm_kernel(const float* __restrict__ A, const float* __restrict__ W,
                 const float* __restrict__ bias, const float* __restrict__ resid,
                 float* __restrict__ C, int M, int N, int K, int do_gelu) {
    __shared__ float As[BKK][BM];
    __shared__ float Bs[BKK][BN];

    int tx = threadIdx.x & 15;   // 0..15  -> col groups of 8
    int ty = threadIdx.x >> 4;   // 0..15  -> row groups of 8
    int tid = threadIdx.x;
    int row0 = blockIdx.y * BM;
    int col0 = blockIdx.x * BN;

    float acc[8][8];
#pragma unroll
    for (int i = 0; i < 8; i++)
#pragma unroll
        for (int j = 0; j < 8; j++) acc[i][j] = 0.f;

    for (int k0 = 0; k0 < K; k0 += BKK) {
        // Load A tile (BM x BK = 1024 floats), 4 per thread, consecutive k
#pragma unroll
        for (int i = 0; i < 4; i++) {
            int idx = tid * 4 + i;          // 0..1023
            int m = idx >> 3;
            int kk = idx & 7;
            int gr = row0 + m;
            float val = 0.f;
            if (gr < M) val = A[(size_t)gr * K + k0 + kk];
            As[kk][m] = val;
        }
        // Load W tile (BK x BN = 1024 floats), coalesced along N
#pragma unroll
        for (int i = 0; i < 4; i++) {
            int idx = i * 256 + tid;        // 0..1023
            int kk = idx >> 7;
            int n = idx & 127;
            Bs[kk][n] = W[(size_t)(k0 + kk) * N + col0 + n];
        }
        __syncthreads();

#pragma unroll
        for (int kk = 0; kk < BKK; kk++) {
            float a[8], b[8];
#pragma unroll
            for (int i = 0; i < 8; i++) a[i] = As[kk][ty * 8 + i];
#pragma unroll
            for (int j = 0; j < 8; j++) b[j] = Bs[kk][tx * 8 + j];
#pragma unroll
            for (int i = 0; i < 8; i++)
#pragma unroll
                for (int j = 0; j < 8; j++)
                    acc[i][j] += a[i] * b[j];
        }
        __syncthreads();
    }

    // Epilogue
#pragma unroll
    for (int i = 0; i < 8; i++) {
        int r = row0 + ty * 8 + i;
        if (r >= M) continue;
#pragma unroll
        for (int j = 0; j < 8; j++) {
            int c = col0 + tx * 8 + j;
            float v = acc[i][j];
            if (bias) v += bias[c];
            if (do_gelu) v = 0.5f * v * (1.0f + erff(v * 0.70710678118654752f));
            if (resid) v += resid[(size_t)r * N + c];
            C[(size_t)r * N + c] = v;
        }
    }
}

// ---------------------------------------------------------------------------
// Fused attention: one block handles TQ=4 query rows for one (b,h).
//   q layout: [B, T, NH, HD] flattened; k/v: [B, Slen, NH, HD] flattened.
//   In-SMEM softmax over Slen (<= 1024).
// ---------------------------------------------------------------------------
#define TQ 4

__global__ void attn_kernel(const float* __restrict__ q, const float* __restrict__ k,
                            const float* __restrict__ v, float* __restrict__ o,
                            int Slen) {
    int b = blockIdx.z;
    int h = blockIdx.y;
    int tq0 = blockIdx.x * TQ;
    int tid = threadIdx.x;       // 128 threads, 4 warps
    int wid = tid >> 5, lane = tid & 31;

    __shared__ float sq[TQ][HD];
    __shared__ float sc[TQ][1024];
    __shared__ float redm[TQ][4];
    __shared__ float reds[TQ][4];

    // Load TQ scaled query rows
    for (int i = tid; i < TQ * HD; i += 128) {
        int qi = i / HD, d = i % HD;
        sq[qi][d] = q[((size_t)(b * T + tq0 + qi) * H) + h * HD + d] * 0.125f; // 1/sqrt(64)
    }
    __syncthreads();

    // Scores
    float lmax[TQ];
#pragma unroll
    for (int qi = 0; qi < TQ; qi++) lmax[qi] = -1e30f;

    for (int j = tid; j < Slen; j += 128) {
        const float* kr = k + ((size_t)(b * Slen + j) * H) + h * HD;
        float dot[TQ] = {0.f, 0.f, 0.f, 0.f};
#pragma unroll 8
        for (int d = 0; d < HD; d++) {
            float kv = kr[d];
#pragma unroll
            for (int qi = 0; qi < TQ; qi++) dot[qi] += sq[qi][d] * kv;
        }
#pragma unroll
        for (int qi = 0; qi < TQ; qi++) {
            sc[qi][j] = dot[qi];
            lmax[qi] = fmaxf(lmax[qi], dot[qi]);
        }
    }

    // Block max per query
#pragma unroll
    for (int qi = 0; qi < TQ; qi++) {
        float wm = warpMax(lmax[qi]);
        if (lane == 0) redm[qi][wid] = wm;
    }
    __syncthreads();
    float m[TQ];
#pragma unroll
    for (int qi = 0; qi < TQ; qi++)
        m[qi] = fmaxf(fmaxf(redm[qi][0], redm[qi][1]), fmaxf(redm[qi][2], redm[qi][3]));

    // exp + sum
    float lsum[TQ] = {0.f, 0.f, 0.f, 0.f};
    for (int j = tid; j < Slen; j += 128) {
#pragma unroll
        for (int qi = 0; qi < TQ; qi++) {
            float e = expf(sc[qi][j] - m[qi]);
            sc[qi][j] = e;
            lsum[qi] += e;
        }
    }
#pragma unroll
    for (int qi = 0; qi < TQ; qi++) {
        float ws = warpSum(lsum[qi]);
        if (lane == 0) reds[qi][wid] = ws;
    }
    __syncthreads();
    float inv[TQ];
#pragma unroll
    for (int qi = 0; qi < TQ; qi++)
        inv[qi] = 1.0f / (reds[qi][0] + reds[qi][1] + reds[qi][2] + reds[qi][3]);

    // Output: threads 0..63 each own one head dim
    if (tid < HD) {
        int d = tid;
        float acc[TQ] = {0.f, 0.f, 0.f, 0.f};
        for (int j = 0; j < Slen; j++) {
            float vv = v[((size_t)(b * Slen + j) * H) + h * HD + d];
#pragma unroll
            for (int qi = 0; qi < TQ; qi++) acc[qi] += sc[qi][j] * vv;
        }
#pragma unroll
        for (int qi = 0; qi < TQ; qi++)
            o[((size_t)(b * T + tq0 + qi) * H) + h * HD + d] = acc[qi] * inv[qi];
    }
}

// ---------------------------------------------------------------------------
// Launch orchestration
// ---------------------------------------------------------------------------
static inline void gemm(const float* A, const float* W, const float* bias,
                        const float* resid, float* C, int M, int N, int K, int gelu) {
    dim3 grid(N / BN, (M + BM - 1) / BM);
    gemm_kernel<<<grid, 256>>>(A, W, bias, resid, C, M, N, K, gelu);
}

extern "C" void kernel_launch(void* const* d_in, const int* in_sizes, int n_in,
                              void* d_out, int out_size) {
    const float* x    = (const float*)d_in[0];
    const float* ctx  = (const float*)d_in[1];
    const float* sq_w = (const float*)d_in[2];
    const float* sk_w = (const float*)d_in[3];
    const float* sv_w = (const float*)d_in[4];
    const float* so_w = (const float*)d_in[5];
    const float* so_b = (const float*)d_in[6];
    const float* cq_w = (const float*)d_in[7];
    const float* ck_w = (const float*)d_in[8];
    const float* cv_w = (const float*)d_in[9];
    const float* co_w = (const float*)d_in[10];
    const float* co_b = (const float*)d_in[11];
    const float* n1_g = (const float*)d_in[12];
    const float* n1_b = (const float*)d_in[13];
    const float* n2_g = (const float*)d_in[14];
    const float* n2_b = (const float*)d_in[15];
    const float* n3_g = (const float*)d_in[16];
    const float* n3_b = (const float*)d_in[17];
    const float* n4_g = (const float*)d_in[18];
    const float* n4_b = (const float*)d_in[19];
    const float* f1_w1 = (const float*)d_in[20];
    const float* f1_b1 = (const float*)d_in[21];
    const float* f1_w2 = (const float*)d_in[22];
    const float* f1_b2 = (const float*)d_in[23];
    const float* f2_w1 = (const float*)d_in[24];
    const float* f2_b1 = (const float*)d_in[25];
    const float* f2_w2 = (const float*)d_in[26];
    const float* f2_b2 = (const float*)d_in[27];
    float* out = (float*)d_out;

    float *px, *pln, *pq, *pk, *pv, *pa, *ph;
    cudaGetSymbolAddress((void**)&px, g_x);
    cudaGetSymbolAddress((void**)&pln, g_ln);
    cudaGetSymbolAddress((void**)&pq, g_q);
    cudaGetSymbolAddress((void**)&pk, g_k);
    cudaGetSymbolAddress((void**)&pv, g_v);
    cudaGetSymbolAddress((void**)&pa, g_attn);
    cudaGetSymbolAddress((void**)&ph, g_h);

    const int NTOK = BT * H;

    // seed residual stream
    copy_kernel<<<(NTOK + 255) / 256, 256>>>(x, px, NTOK);

    // ---------------- Stage A: self-attention ----------------
    ln_kernel<<<BT, 256>>>(px, n1_g, n1_b, pln);
    gemm(pln, sq_w, nullptr, nullptr, pq, BT, H, H, 0);
    gemm(pln, sk_w, nullptr, nullptr, pk, BT, H, H, 0);
    gemm(pln, sv_w, nullptr, nullptr, pv, BT, H, H, 0);
    attn_kernel<<<dim3(T / TQ, NH, BATCH), 128>>>(pq, pk, pv, pa, T);
    gemm(pa, so_w, so_b, px, px, BT, H, H, 0);

    // ---------------- Stage B: FFN 1 ----------------
    ln_kernel<<<BT, 256>>>(px, n2_g, n2_b, pln);
    gemm(pln, f1_w1, f1_b1, nullptr, ph, BT, FF, H, 1);
    gemm(ph, f1_w2, f1_b2, px, px, BT, H, FF, 0);

    // ---------------- Stage C: cross-attention ----------------
    ln_kernel<<<BT, 256>>>(px, n3_g, n3_b, pln);
    gemm(pln, cq_w, nullptr, nullptr, pq, BT, H, H, 0);
    gemm(ctx, ck_w, nullptr, nullptr, pk, BATCH * SC, H, CD, 0);
    gemm(ctx, cv_w, nullptr, nullptr, pv, BATCH * SC, H, CD, 0);
    attn_kernel<<<dim3(T / TQ, NH, BATCH), 128>>>(pq, pk, pv, pa, SC);
    gemm(pa, co_w, co_b, px, px, BT, H, H, 0);

    // ---------------- Stage D: FFN 2 ----------------
    ln_kernel<<<BT, 256>>>(px, n4_g, n4_b, pln);
    gemm(pln, f2_w1, f2_b1, nullptr, ph, BT, FF, H, 1);
    gemm(ph, f2_w2, f2_b2, px, out, BT, H, FF, 0);
}

// round 2
// speedup vs baseline: 2.6910x; 2.6910x over previous
#include <cuda_runtime.h>
#include <math.h>
#include <stddef.h>
#include <stdint.h>

// ---------------------------------------------------------------------------
// Problem dims (fixed by the dataset)
// ---------------------------------------------------------------------------
#define BATCH 4
#define T 1024
#define H 1024
#define NH 16
#define HD 64
#define CD 768
#define SC 77
#define FF 4096
#define BT (BATCH * T)

// ---------------------------------------------------------------------------
// Scratch (static device globals; no runtime allocation allowed)
// ---------------------------------------------------------------------------
__device__ float g_x[BT * H];
__device__ float g_ln[BT * H];
__device__ float g_q[BT * H];
__device__ float g_k[BT * H];
__device__ float g_v[BT * H];
__device__ float g_attn[BT * H];
__device__ float g_h[BT * FF];

// ---------------------------------------------------------------------------
// Utility
// ---------------------------------------------------------------------------
__device__ __forceinline__ float warpMax(float v) {
#pragma unroll
    for (int o = 16; o; o >>= 1) v = fmaxf(v, __shfl_xor_sync(0xffffffffu, v, o));
    return v;
}
__device__ __forceinline__ float warpSum(float v) {
#pragma unroll
    for (int o = 16; o; o >>= 1) v += __shfl_xor_sync(0xffffffffu, v, o);
    return v;
}
__device__ __forceinline__ float tf32r(float x) {
    uint32_t u;
    asm("cvt.rna.tf32.f32 %0, %1;" : "=r"(u) : "f"(x));
    return __uint_as_float(u);
}
__device__ __forceinline__ void mma_tf32(float* c, const uint32_t* a, const uint32_t* b) {
    asm volatile(
        "mma.sync.aligned.m16n8k8.row.col.f32.tf32.tf32.f32 "
        "{%0,%1,%2,%3}, {%4,%5,%6,%7}, {%8,%9}, {%0,%1,%2,%3};"
        : "+f"(c[0]), "+f"(c[1]), "+f"(c[2]), "+f"(c[3])
        : "r"(a[0]), "r"(a[1]), "r"(a[2]), "r"(a[3]), "r"(b[0]), "r"(b[1]));
}

// ---------------------------------------------------------------------------
// Copy kernel
// ---------------------------------------------------------------------------
__global__ void copy_kernel(const float4* __restrict__ in, float4* __restrict__ out, int n4) {
    int i = blockIdx.x * blockDim.x + threadIdx.x;
    if (i < n4) out[i] = in[i];
}

// ---------------------------------------------------------------------------
// LayerNorm: one block per row of H=1024
// ---------------------------------------------------------------------------
__global__ void ln_kernel(const float* __restrict__ in,
                          const float* __restrict__ gamma,
                          const float* __restrict__ beta,
                          float* __restrict__ out) {
    int row = blockIdx.x;
    const float* r = in + (size_t)row * H;
    int tid = threadIdx.x;

    float s = 0.f, s2 = 0.f;
    for (int i = tid; i < H; i += 256) {
        float v = r[i];
        s += v; s2 += v * v;
    }
    __shared__ float sh_s[8], sh_s2[8];
    float ws = warpSum(s), ws2 = warpSum(s2);
    int wid = tid >> 5, lane = tid & 31;
    if (lane == 0) { sh_s[wid] = ws; sh_s2[wid] = ws2; }
    __syncthreads();
    float tot = 0.f, tot2 = 0.f;
#pragma unroll
    for (int w = 0; w < 8; w++) { tot += sh_s[w]; tot2 += sh_s2[w]; }
    float mean = tot * (1.0f / H);
    float var = tot2 * (1.0f / H) - mean * mean;
    float inv = rsqrtf(var + 1e-5f);

    float* o = out + (size_t)row * H;
    for (int i = tid; i < H; i += 256) {
        o[i] = (r[i] - mean) * inv * gamma[i] + beta[i];
    }
}

// ---------------------------------------------------------------------------
// TF32 tensor-core GEMM: C[M,N] = A[M,K] @ W[K,N] (+bias)(+GELU)(+residual)
//   BM=128, BN=128, BK=32; 256 threads (8 warps), warp tile 32x64.
//   mma.sync m16n8k8 tf32. K % 32 == 0, N % 128 == 0; M guarded.
// ---------------------------------------------------------------------------
#define GBM 128
#define GBN 128
#define GBK 32
#define ASTR (GBM + 4)
#define BSTR (GBN + 4)

__global__ __launch_bounds__(256, 2)
void gemm_tf32_kernel(const float* __restrict__ A, const float* __restrict__ W,
                      const float* __restrict__ bias, const float* __restrict__ resid,
                      float* __restrict__ C, int M, int N, int K, int do_gelu) {
    __shared__ float As[GBK][ASTR];   // [k][m]
    __shared__ float Bs[GBK][BSTR];   // [k][n]

    int tid = threadIdx.x;
    int lane = tid & 31;
    int w = tid >> 5;
    int g = lane >> 2;    // 0..7
    int t = lane & 3;     // 0..3
    int wm = w & 3;       // 0..3 (row quadrant, 32 rows)
    int wn = w >> 2;      // 0..1 (col half, 64 cols)
    int row0 = blockIdx.y * GBM;
    int col0 = blockIdx.x * GBN;

    float c[2][8][4];
#pragma unroll
    for (int mt = 0; mt < 2; mt++)
#pragma unroll
        for (int nt = 0; nt < 8; nt++)
#pragma unroll
            for (int i = 0; i < 4; i++) c[mt][nt][i] = 0.f;

    for (int k0 = 0; k0 < K; k0 += GBK) {
        // --- load A tile (128 x 32), transpose into As[k][m], convert to tf32
#pragma unroll
        for (int i = 0; i < 4; i++) {
            int fidx = i * 256 + tid;      // 0..1023 float4 units
            int m = fidx >> 3;             // 0..127
            int kq = fidx & 7;             // float4 index along k
            int gr = row0 + m;
            float4 v = make_float4(0.f, 0.f, 0.f, 0.f);
            if (gr < M) v = *(const float4*)(A + (size_t)gr * K + k0 + kq * 4);
            As[kq * 4 + 0][m] = tf32r(v.x);
            As[kq * 4 + 1][m] = tf32r(v.y);
            As[kq * 4 + 2][m] = tf32r(v.z);
            As[kq * 4 + 3][m] = tf32r(v.w);
        }
        // --- load B tile (32 x 128) into Bs[k][n], convert to tf32
#pragma unroll
        for (int i = 0; i < 4; i++) {
            int fidx = i * 256 + tid;      // 0..1023 float4 units
            int kk = fidx >> 5;            // 0..31
            int nq = fidx & 31;            // 0..31 float4 along n
            float4 v = *(const float4*)(W + (size_t)(k0 + kk) * N + col0 + nq * 4);
            float4 o;
            o.x = tf32r(v.x); o.y = tf32r(v.y); o.z = tf32r(v.z); o.w = tf32r(v.w);
            *(float4*)&Bs[kk][nq * 4] = o;
        }
        __syncthreads();

#pragma unroll
        for (int kk = 0; kk < GBK; kk += 8) {
            uint32_t a[2][4], b[8][2];
#pragma unroll
            for (int mt = 0; mt < 2; mt++) {
                int m = wm * 32 + mt * 16 + g;
                a[mt][0] = __float_as_uint(As[kk + t][m]);
                a[mt][1] = __float_as_uint(As[kk + t][m + 8]);
                a[mt][2] = __float_as_uint(As[kk + t + 4][m]);
                a[mt][3] = __float_as_uint(As[kk + t + 4][m + 8]);
            }
#pragma unroll
            for (int nt = 0; nt < 8; nt++) {
                int n = wn * 64 + nt * 8 + g;
                b[nt][0] = __float_as_uint(Bs[kk + t][n]);
                b[nt][1] = __float_as_uint(Bs[kk + t + 4][n]);
            }
#pragma unroll
            for (int mt = 0; mt < 2; mt++)
#pragma unroll
                for (int nt = 0; nt < 8; nt++)
                    mma_tf32(c[mt][nt], a[mt], b[nt]);
        }
        __syncthreads();
    }

    // --- epilogue
#pragma unroll
    for (int mt = 0; mt < 2; mt++) {
        int r = row0 + wm * 32 + mt * 16 + g;
#pragma unroll
        for (int nt = 0; nt < 8; nt++) {
            int cc = col0 + wn * 64 + nt * 8 + 2 * t;
            float v0 = c[mt][nt][0], v1 = c[mt][nt][1];
            float v2 = c[mt][nt][2], v3 = c[mt][nt][3];
            if (bias) {
                float b0 = bias[cc], b1 = bias[cc + 1];
                v0 += b0; v1 += b1; v2 += b0; v3 += b1;
            }
            if (do_gelu) {
                v0 = 0.5f * v0 * (1.0f + erff(v0 * 0.70710678118654752f));
                v1 = 0.5f * v1 * (1.0f + erff(v1 * 0.70710678118654752f));
                v2 = 0.5f * v2 * (1.0f + erff(v2 * 0.70710678118654752f));
                v3 = 0.5f * v3 * (1.0f + erff(v3 * 0.70710678118654752f));
            }
            if (r < M) {
                if (resid) { v0 += resid[(size_t)r * N + cc]; v1 += resid[(size_t)r * N + cc + 1]; }
                C[(size_t)r * N + cc] = v0;
                C[(size_t)r * N + cc + 1] = v1;
            }
            if (r + 8 < M) {
                if (resid) { v2 += resid[(size_t)(r + 8) * N + cc]; v3 += resid[(size_t)(r + 8) * N + cc + 1]; }
                C[(size_t)(r + 8) * N + cc] = v2;
                C[(size_t)(r + 8) * N + cc + 1] = v3;
            }
        }
    }
}

// ---------------------------------------------------------------------------
// Fused attention, tiled through SMEM.
//   Block: 256 threads (8 warps). Warp w owns query (tq0 + w).
//   K/V staged in SMEM tiles of 128 rows x 64 dims (stride 65, conflict-free).
//   q layout: [B, T, NH, HD] flattened; k/v: [B, Slen, NH, HD] flattened.
// ---------------------------------------------------------------------------
#define ATQ 8
#define ATILE 128
#define KVSTR 65
// dynamic smem: sq (8*64) + kv (128*65) + sc (8*1024)
#define SQ_OFF 0
#define KV_OFF (ATQ * HD)
#define SC_OFF (KV_OFF + ATILE * KVSTR)
#define ATTN_SMEM_FLOATS (SC_OFF + ATQ * 1024)
#define ATTN_SMEM_BYTES (ATTN_SMEM_FLOATS * 4)

__global__ __launch_bounds__(256, 2)
void attn_kernel(const float* __restrict__ q, const float* __restrict__ k,
                 const float* __restrict__ v, float* __restrict__ o, int Slen) {
    extern __shared__ float sm[];
    float* sq = sm + SQ_OFF;
    float* kv = sm + KV_OFF;
    float* sc = sm + SC_OFF;

    int b = blockIdx.z;
    int h = blockIdx.y;
    int tq0 = blockIdx.x * ATQ;
    int tid = threadIdx.x;
    int w = tid >> 5, lane = tid & 31;

    // load + scale queries
    for (int i = tid; i < ATQ * HD; i += 256) {
        int qi = i >> 6, d = i & 63;
        sq[i] = q[((size_t)(b * T + tq0 + qi) * H) + h * HD + d] * 0.125f;
    }

    // ---- phase 1: scores (warp w owns query w)
    float lmax = -1e30f;
    for (int j0 = 0; j0 < Slen; j0 += ATILE) {
        int rows = Slen - j0; if (rows > ATILE) rows = ATILE;
        __syncthreads();
        for (int i = tid; i < ATILE * HD; i += 256) {
            int r = i >> 6, d = i & 63;
            float val = 0.f;
            if (r < rows) val = k[((size_t)(b * Slen + j0 + r) * H) + h * HD + d];
            kv[r * KVSTR + d] = val;
        }
        __syncthreads();

        float dot0 = 0.f, dot1 = 0.f, dot2 = 0.f, dot3 = 0.f;
        const float* sqw = sq + w * HD;
#pragma unroll 8
        for (int d = 0; d < HD; d++) {
            float s = sqw[d];
            dot0 += s * kv[(lane) * KVSTR + d];
            dot1 += s * kv[(lane + 32) * KVSTR + d];
            dot2 += s * kv[(lane + 64) * KVSTR + d];
            dot3 += s * kv[(lane + 96) * KVSTR + d];
        }
        float dots[4] = {dot0, dot1, dot2, dot3};
#pragma unroll
        for (int u = 0; u < 4; u++) {
            int jj = lane + 32 * u;
            if (jj < rows) {
                sc[w * 1024 + j0 + jj] = dots[u];
                lmax = fmaxf(lmax, dots[u]);
            }
        }
    }

    // ---- phase 2: softmax (warp-private)
    float m = warpMax(lmax);
    float lsum = 0.f;
    for (int j = lane; j < Slen; j += 32) {
        float e = __expf(sc[w * 1024 + j] - m);
        sc[w * 1024 + j] = e;
        lsum += e;
    }
    float inv = 1.0f / warpSum(lsum);

    // ---- phase 3: O = P @ V   (lane owns dims lane, lane+32)
    float acc0 = 0.f, acc1 = 0.f;
    for (int j0 = 0; j0 < Slen; j0 += ATILE) {
        int rows = Slen - j0; if (rows > ATILE) rows = ATILE;
        __syncthreads();
        for (int i = tid; i < ATILE * HD; i += 256) {
            int r = i >> 6, d = i & 63;
            float val = 0.f;
            if (r < rows) val = v[((size_t)(b * Slen + j0 + r) * H) + h * HD + d];
            kv[r * KVSTR + d] = val;
        }
        __syncthreads();

        const float* scw = sc + w * 1024 + j0;
        for (int jj = 0; jj < rows; jj++) {
            float p = scw[jj];
            acc0 += p * kv[jj * KVSTR + lane];
            acc1 += p * kv[jj * KVSTR + lane + 32];
        }
    }
    size_t obase = ((size_t)(b * T + tq0 + w) * H) + h * HD;
    o[obase + lane] = acc0 * inv;
    o[obase + lane + 32] = acc1 * inv;
}

// ---------------------------------------------------------------------------
// Launch orchestration
// ---------------------------------------------------------------------------
static inline void gemm(const float* A, const float* W, const float* bias,
                        const float* resid, float* C, int M, int N, int K, int gelu) {
    dim3 grid(N / GBN, (M + GBM - 1) / GBM);
    gemm_tf32_kernel<<<grid, 256>>>(A, W, bias, resid, C, M, N, K, gelu);
}

extern "C" void kernel_launch(void* const* d_in, const int* in_sizes, int n_in,
                              void* d_out, int out_size) {
    const float* x    = (const float*)d_in[0];
    const float* ctx  = (const float*)d_in[1];
    const float* sq_w = (const float*)d_in[2];
    const float* sk_w = (const float*)d_in[3];
    const float* sv_w = (const float*)d_in[4];
    const float* so_w = (const float*)d_in[5];
    const float* so_b = (const float*)d_in[6];
    const float* cq_w = (const float*)d_in[7];
    const float* ck_w = (const float*)d_in[8];
    const float* cv_w = (const float*)d_in[9];
    const float* co_w = (const float*)d_in[10];
    const float* co_b = (const float*)d_in[11];
    const float* n1_g = (const float*)d_in[12];
    const float* n1_b = (const float*)d_in[13];
    const float* n2_g = (const float*)d_in[14];
    const float* n2_b = (const float*)d_in[15];
    const float* n3_g = (const float*)d_in[16];
    const float* n3_b = (const float*)d_in[17];
    const float* n4_g = (const float*)d_in[18];
    const float* n4_b = (const float*)d_in[19];
    const float* f1_w1 = (const float*)d_in[20];
    const float* f1_b1 = (const float*)d_in[21];
    const float* f1_w2 = (const float*)d_in[22];
    const float* f1_b2 = (const float*)d_in[23];
    const float* f2_w1 = (const float*)d_in[24];
    const float* f2_b1 = (const float*)d_in[25];
    const float* f2_w2 = (const float*)d_in[26];
    const float* f2_b2 = (const float*)d_in[27];
    float* out = (float*)d_out;

    float *px, *pln, *pq, *pk, *pv, *pa, *ph;
    cudaGetSymbolAddress((void**)&px, g_x);
    cudaGetSymbolAddress((void**)&pln, g_ln);
    cudaGetSymbolAddress((void**)&pq, g_q);
    cudaGetSymbolAddress((void**)&pk, g_k);
    cudaGetSymbolAddress((void**)&pv, g_v);
    cudaGetSymbolAddress((void**)&pa, g_attn);
    cudaGetSymbolAddress((void**)&ph, g_h);

    cudaFuncSetAttribute(attn_kernel, cudaFuncAttributeMaxDynamicSharedMemorySize,
                         ATTN_SMEM_BYTES);

    const int NTOK = BT * H;

    // seed residual stream
    copy_kernel<<<(NTOK / 4 + 255) / 256, 256>>>((const float4*)x, (float4*)px, NTOK / 4);

    // ---------------- Stage A: self-attention ----------------
    ln_kernel<<<BT, 256>>>(px, n1_g, n1_b, pln);
    gemm(pln, sq_w, nullptr, nullptr, pq, BT, H, H, 0);
    gemm(pln, sk_w, nullptr, nullptr, pk, BT, H, H, 0);
    gemm(pln, sv_w, nullptr, nullptr, pv, BT, H, H, 0);
    attn_kernel<<<dim3(T / ATQ, NH, BATCH), 256, ATTN_SMEM_BYTES>>>(pq, pk, pv, pa, T);
    gemm(pa, so_w, so_b, px, px, BT, H, H, 0);

    // ---------------- Stage B: FFN 1 ----------------
    ln_kernel<<<BT, 256>>>(px, n2_g, n2_b, pln);
    gemm(pln, f1_w1, f1_b1, nullptr, ph, BT, FF, H, 1);
    gemm(ph, f1_w2, f1_b2, px, px, BT, H, FF, 0);

    // ---------------- Stage C: cross-attention ----------------
    ln_kernel<<<BT, 256>>>(px, n3_g, n3_b, pln);
    gemm(pln, cq_w, nullptr, nullptr, pq, BT, H, H, 0);
    gemm(ctx, ck_w, nullptr, nullptr, pk, BATCH * SC, H, CD, 0);
    gemm(ctx, cv_w, nullptr, nullptr, pv, BATCH * SC, H, CD, 0);
    attn_kernel<<<dim3(T / ATQ, NH, BATCH), 256, ATTN_SMEM_BYTES>>>(pq, pk, pv, pa, SC);
    gemm(pa, co_w, co_b, px, px, BT, H, H, 0);

    // ---------------- Stage D: FFN 2 ----------------
    ln_kernel<<<BT, 256>>>(px, n4_g, n4_b, pln);
    gemm(pln, f2_w1, f2_b1, nullptr, ph, BT, FF, H, 1);
    gemm(ph, f2_w2, f2_b2, px, out, BT, H, FF, 0);
}

// round 4
// speedup vs baseline: 3.7160x; 1.3809x over previous
#include <cuda_runtime.h>
#include <cuda_fp16.h>
#include <math.h>
#include <stddef.h>
#include <stdint.h>

// ---------------------------------------------------------------------------
// Problem dims
// ---------------------------------------------------------------------------
#define BATCH 4
#define T 1024
#define H 1024
#define NH 16
#define HD 64
#define CD 768
#define SC 77
#define FF 4096
#define BT (BATCH * T)

// ---------------------------------------------------------------------------
// Scratch
// ---------------------------------------------------------------------------
__device__ float g_x[BT * H];         // residual stream (fp32)
__device__ float g_q[BT * H];
__device__ float g_k[BT * H];
__device__ float g_v[BT * H];
__device__ __half g_ln_h[BT * H];     // LN output (fp16, GEMM A operand)
__device__ __half g_attn_h[BT * H];   // attention output (fp16)
__device__ __half g_hid_h[BT * FF];   // FFN hidden (fp16)
__device__ __half g_ctx_h[BATCH * SC * CD];
// transposed fp16 weights, [N,K] row-major
#define WT_Q   0
#define WT_K   (WT_Q + H * H)
#define WT_V   (WT_K + H * H)
#define WT_O   (WT_V + H * H)
#define WT_CQ  (WT_O + H * H)
#define WT_CO  (WT_CQ + H * H)
#define WT_CK  (WT_CO + H * H)
#define WT_CV  (WT_CK + H * CD)
#define WT_F1A (WT_CV + H * CD)
#define WT_F1B (WT_F1A + FF * H)
#define WT_F2A (WT_F1B + H * FF)
#define WT_F2B (WT_F2A + FF * H)
#define WT_TOTAL (WT_F2B + H * FF)
__device__ __half g_wt[WT_TOTAL];

// ---------------------------------------------------------------------------
// Utility
// ---------------------------------------------------------------------------
__device__ __forceinline__ float warpMax(float v) {
#pragma unroll
    for (int o = 16; o; o >>= 1) v = fmaxf(v, __shfl_xor_sync(0xffffffffu, v, o));
    return v;
}
__device__ __forceinline__ float warpSum(float v) {
#pragma unroll
    for (int o = 16; o; o >>= 1) v += __shfl_xor_sync(0xffffffffu, v, o);
    return v;
}
__device__ __forceinline__ uint32_t smem_u32(const void* p) {
    uint32_t a;
    asm("{ .reg .u64 t; cvta.to.shared.u64 t, %1; cvt.u32.u64 %0, t; }" : "=r"(a) : "l"(p));
    return a;
}
__device__ __forceinline__ void cp16(uint32_t saddr, const void* g, int srcBytes) {
    asm volatile("cp.async.cg.shared.global [%0], [%1], 16, %2;"
                 :: "r"(saddr), "l"(g), "r"(srcBytes) : "memory");
}
#define CP_COMMIT() asm volatile("cp.async.commit_group;" ::: "memory")
#define CP_WAIT1()  asm volatile("cp.async.wait_group 1;" ::: "memory")

__device__ __forceinline__ void mma_f16(float* c, const uint32_t* a, const uint32_t* b) {
    asm volatile(
        "mma.sync.aligned.m16n8k16.row.col.f32.f16.f16.f32 "
        "{%0,%1,%2,%3}, {%4,%5,%6,%7}, {%8,%9}, {%0,%1,%2,%3};"
        : "+f"(c[0]), "+f"(c[1]), "+f"(c[2]), "+f"(c[3])
        : "r"(a[0]), "r"(a[1]), "r"(a[2]), "r"(a[3]), "r"(b[0]), "r"(b[1]));
}

// ---------------------------------------------------------------------------
// Small kernels
// ---------------------------------------------------------------------------
__global__ void copy_kernel(const float4* __restrict__ in, float4* __restrict__ out, int n4) {
    int i = blockIdx.x * blockDim.x + threadIdx.x;
    if (i < n4) out[i] = in[i];
}
__global__ void f2h_kernel(const float* __restrict__ in, __half* __restrict__ out, int n) {
    int i = blockIdx.x * blockDim.x + threadIdx.x;
    if (i < n) out[i] = __float2half(in[i]);
}
// transpose + fp16: in[K,N] -> out[N,K]
__global__ void transpose_kernel(const float* __restrict__ in, __half* __restrict__ out,
                                 int K, int N) {
    __shared__ float t[32][33];
    int k0 = blockIdx.y * 32, n0 = blockIdx.x * 32;
    int tx = threadIdx.x & 31, ty = threadIdx.x >> 5;
#pragma unroll
    for (int i = 0; i < 32; i += 8)
        t[ty + i][tx] = in[(size_t)(k0 + ty + i) * N + n0 + tx];
    __syncthreads();
#pragma unroll
    for (int i = 0; i < 32; i += 8)
        out[(size_t)(n0 + ty + i) * K + k0 + tx] = __float2half(t[tx][ty + i]);
}

// ---------------------------------------------------------------------------
// LayerNorm: fp32 in -> fp16 out
// ---------------------------------------------------------------------------
__global__ void ln_kernel(const float* __restrict__ in,
                          const float* __restrict__ gamma,
                          const float* __restrict__ beta,
                          __half* __restrict__ out) {
    int row = blockIdx.x;
    const float* r = in + (size_t)row * H;
    int tid = threadIdx.x;

    float s = 0.f, s2 = 0.f;
    for (int i = tid; i < H; i += 256) {
        float v = r[i];
        s += v; s2 += v * v;
    }
    __shared__ float sh_s[8], sh_s2[8];
    float ws = warpSum(s), ws2 = warpSum(s2);
    int wid = tid >> 5, lane = tid & 31;
    if (lane == 0) { sh_s[wid] = ws; sh_s2[wid] = ws2; }
    __syncthreads();
    float tot = 0.f, tot2 = 0.f;
#pragma unroll
    for (int w = 0; w < 8; w++) { tot += sh_s[w]; tot2 += sh_s2[w]; }
    float mean = tot * (1.0f / H);
    float var = tot2 * (1.0f / H) - mean * mean;
    float inv = rsqrtf(var + 1e-5f);

    __half* o = out + (size_t)row * H;
    for (int i = tid; i < H; i += 256) {
        o[i] = __float2half((r[i] - mean) * inv * gamma[i] + beta[i]);
    }
}

// ---------------------------------------------------------------------------
// FP16 tensor-core GEMM: C[M,N] = A[M,K] @ Wt[N,K]^T  (+bias)(+GELU)(+resid)
//   Tile 128x128x32, 256 threads (8 warps, warp tile 32x64), 2-stage cp.async.
//   Outputs: Cf (fp32, optional) and/or Ch (fp16, optional).
//   K % 32 == 0, N % 128 == 0; M guarded.
// ---------------------------------------------------------------------------
#define KSTR 40   // halves per SMEM row (32 + 8 pad)

__global__ __launch_bounds__(256, 2)
void gemm_h_kernel(const __half* __restrict__ A, const __half* __restrict__ Wt,
                   const float* __restrict__ bias, const float* __restrict__ resid,
                   float* __restrict__ Cf, __half* __restrict__ Ch,
                   int M, int N, int K, int do_gelu) {
    __shared__ __half sA[2][128 * KSTR];
    __shared__ __half sB[2][128 * KSTR];

    int tid = threadIdx.x;
    int lane = tid & 31, w = tid >> 5;
    int g = lane >> 2, t = lane & 3;
    int wm = w & 3, wn = w >> 2;
    int row0 = blockIdx.y * 128;
    int col0 = blockIdx.x * 128;

    uint32_t sAb[2] = { smem_u32(sA[0]), smem_u32(sA[1]) };
    uint32_t sBb[2] = { smem_u32(sB[0]), smem_u32(sB[1]) };

    // loader indices: 512 chunks of 16B per tile; 2 per thread
    int ldrow[2], ldc16[2];
#pragma unroll
    for (int i = 0; i < 2; i++) {
        int idx = i * 256 + tid;
        ldrow[i] = idx >> 2;
        ldc16[i] = idx & 3;
    }

    const int NK = K >> 5;

    // prologue: stage 0
#pragma unroll
    for (int i = 0; i < 2; i++) {
        int r = ldrow[i], c16 = ldc16[i];
        int gr = row0 + r;
        const __half* ga = A + (size_t)(gr < M ? gr : row0) * K + c16 * 8;
        cp16(sAb[0] + (r * KSTR + c16 * 8) * 2, ga, gr < M ? 16 : 0);
        const __half* gb = Wt + (size_t)(col0 + r) * K + c16 * 8;
        cp16(sBb[0] + (r * KSTR + c16 * 8) * 2, gb, 16);
    }
    CP_COMMIT();

    float c[2][8][4];
#pragma unroll
    for (int mt = 0; mt < 2; mt++)
#pragma unroll
        for (int nt = 0; nt < 8; nt++)
#pragma unroll
            for (int i = 0; i < 4; i++) c[mt][nt][i] = 0.f;

    for (int kt = 0; kt < NK; kt++) {
        int s = kt & 1;
        if (kt + 1 < NK) {
            int sn = (kt + 1) & 1;
            int k0 = (kt + 1) << 5;
#pragma unroll
            for (int i = 0; i < 2; i++) {
                int r = ldrow[i], c16 = ldc16[i];
                int gr = row0 + r;
                const __half* ga = A + (size_t)(gr < M ? gr : row0) * K + k0 + c16 * 8;
                cp16(sAb[sn] + (r * KSTR + c16 * 8) * 2, ga, gr < M ? 16 : 0);
                const __half* gb = Wt + (size_t)(col0 + r) * K + k0 + c16 * 8;
                cp16(sBb[sn] + (r * KSTR + c16 * 8) * 2, gb, 16);
            }
        }
        CP_COMMIT();
        CP_WAIT1();
        __syncthreads();

        const __half* as = sA[s];
        const __half* bs = sB[s];
#pragma unroll
        for (int ks = 0; ks < 2; ks++) {
            int kb = ks * 16;
            uint32_t a[2][4], b[8][2];
#pragma unroll
            for (int mt = 0; mt < 2; mt++) {
                int m = wm * 32 + mt * 16 + g;
                a[mt][0] = *(const uint32_t*)(as + m * KSTR + kb + 2 * t);
                a[mt][1] = *(const uint32_t*)(as + (m + 8) * KSTR + kb + 2 * t);
                a[mt][2] = *(const uint32_t*)(as + m * KSTR + kb + 2 * t + 8);
                a[mt][3] = *(const uint32_t*)(as + (m + 8) * KSTR + kb + 2 * t + 8);
            }
#pragma unroll
            for (int nt = 0; nt < 8; nt++) {
                int n = wn * 64 + nt * 8 + g;
                b[nt][0] = *(const uint32_t*)(bs + n * KSTR + kb + 2 * t);
                b[nt][1] = *(const uint32_t*)(bs + n * KSTR + kb + 2 * t + 8);
            }
#pragma unroll
            for (int mt = 0; mt < 2; mt++)
#pragma unroll
                for (int nt = 0; nt < 8; nt++)
                    mma_f16(c[mt][nt], a[mt], b[nt]);
        }
        __syncthreads();
    }

    // epilogue
#pragma unroll
    for (int mt = 0; mt < 2; mt++) {
        int r = row0 + wm * 32 + mt * 16 + g;
#pragma unroll
        for (int nt = 0; nt < 8; nt++) {
            int cc = col0 + wn * 64 + nt * 8 + 2 * t;
            float v0 = c[mt][nt][0], v1 = c[mt][nt][1];
            float v2 = c[mt][nt][2], v3 = c[mt][nt][3];
            if (bias) {
                float b0 = bias[cc], b1 = bias[cc + 1];
                v0 += b0; v1 += b1; v2 += b0; v3 += b1;
            }
            if (do_gelu) {
                v0 = 0.5f * v0 * (1.0f + erff(v0 * 0.70710678118654752f));
                v1 = 0.5f * v1 * (1.0f + erff(v1 * 0.70710678118654752f));
                v2 = 0.5f * v2 * (1.0f + erff(v2 * 0.70710678118654752f));
                v3 = 0.5f * v3 * (1.0f + erff(v3 * 0.70710678118654752f));
            }
            if (r < M) {
                float o0 = v0, o1 = v1;
                if (resid) { o0 += resid[(size_t)r * N + cc]; o1 += resid[(size_t)r * N + cc + 1]; }
                if (Cf) { Cf[(size_t)r * N + cc] = o0; Cf[(size_t)r * N + cc + 1] = o1; }
                if (Ch) *(half2*)(Ch + (size_t)r * N + cc) = __floats2half2_rn(o0, o1);
            }
            if (r + 8 < M) {
                float o2 = v2, o3 = v3;
                if (resid) { o2 += resid[(size_t)(r + 8) * N + cc]; o3 += resid[(size_t)(r + 8) * N + cc + 1]; }
                if (Cf) { Cf[(size_t)(r + 8) * N + cc] = o2; Cf[(size_t)(r + 8) * N + cc + 1] = o3; }
                if (Ch) *(half2*)(Ch + (size_t)(r + 8) * N + cc) = __floats2half2_rn(o2, o3);
            }
        }
    }
}

// ---------------------------------------------------------------------------
// Fused attention (fp32 math), writes fp16 output.
// ---------------------------------------------------------------------------
#define ATQ 8
#define ATILE 128
#define KVSTR 65
#define SQ_OFF 0
#define KV_OFF (ATQ * HD)
#define SC_OFF (KV_OFF + ATILE * KVSTR)
#define ATTN_SMEM_FLOATS (SC_OFF + ATQ * 1024)
#define ATTN_SMEM_BYTES (ATTN_SMEM_FLOATS * 4)

__global__ __launch_bounds__(256, 2)
void attn_kernel(const float* __restrict__ q, const float* __restrict__ k,
                 const float* __restrict__ v, __half* __restrict__ o, int Slen) {
    extern __shared__ float smf[];
    float* sq = smf + SQ_OFF;
    float* kv = smf + KV_OFF;
    float* sc = smf + SC_OFF;

    int b = blockIdx.z;
    int h = blockIdx.y;
    int tq0 = blockIdx.x * ATQ;
    int tid = threadIdx.x;
    int w = tid >> 5, lane = tid & 31;

    for (int i = tid; i < ATQ * HD; i += 256) {
        int qi = i >> 6, d = i & 63;
        sq[i] = q[((size_t)(b * T + tq0 + qi) * H) + h * HD + d] * 0.125f;
    }

    float lmax = -1e30f;
    for (int j0 = 0; j0 < Slen; j0 += ATILE) {
        int rows = Slen - j0; if (rows > ATILE) rows = ATILE;
        __syncthreads();
        for (int i = tid; i < ATILE * HD; i += 256) {
            int r = i >> 6, d = i & 63;
            float val = 0.f;
            if (r < rows) val = k[((size_t)(b * Slen + j0 + r) * H) + h * HD + d];
            kv[r * KVSTR + d] = val;
        }
        __syncthreads();

        float dot0 = 0.f, dot1 = 0.f, dot2 = 0.f, dot3 = 0.f;
        const float* sqw = sq + w * HD;
#pragma unroll 8
        for (int d = 0; d < HD; d++) {
            float s = sqw[d];
            dot0 += s * kv[(lane) * KVSTR + d];
            dot1 += s * kv[(lane + 32) * KVSTR + d];
            dot2 += s * kv[(lane + 64) * KVSTR + d];
            dot3 += s * kv[(lane + 96) * KVSTR + d];
        }
        float dots[4] = {dot0, dot1, dot2, dot3};
#pragma unroll
        for (int u = 0; u < 4; u++) {
            int jj = lane + 32 * u;
            if (jj < rows) {
                sc[w * 1024 + j0 + jj] = dots[u];
                lmax = fmaxf(lmax, dots[u]);
            }
        }
    }

    float m = warpMax(lmax);
    float lsum = 0.f;
    for (int j = lane; j < Slen; j += 32) {
        float e = __expf(sc[w * 1024 + j] - m);
        sc[w * 1024 + j] = e;
        lsum += e;
    }
    float inv = 1.0f / warpSum(lsum);

    float a0 = 0.f, a1 = 0.f, a2 = 0.f, a3 = 0.f;   // two dims x 2-way unrolled j
    for (int j0 = 0; j0 < Slen; j0 += ATILE) {
        int rows = Slen - j0; if (rows > ATILE) rows = ATILE;
        __syncthreads();
        for (int i = tid; i < ATILE * HD; i += 256) {
            int r = i >> 6, d = i & 63;
            float val = 0.f;
            if (r < rows) val = v[((size_t)(b * Slen + j0 + r) * H) + h * HD + d];
            kv[r * KVSTR + d] = val;
        }
        __syncthreads();

        const float* scw = sc + w * 1024 + j0;
        int jj = 0;
        for (; jj + 1 < rows; jj += 2) {
            float p0 = scw[jj], p1 = scw[jj + 1];
            a0 += p0 * kv[jj * KVSTR + lane];
            a1 += p0 * kv[jj * KVSTR + lane + 32];
            a2 += p1 * kv[(jj + 1) * KVSTR + lane];
            a3 += p1 * kv[(jj + 1) * KVSTR + lane + 32];
        }
        if (jj < rows) {
            float p0 = scw[jj];
            a0 += p0 * kv[jj * KVSTR + lane];
            a1 += p0 * kv[jj * KVSTR + lane + 32];
        }
    }
    size_t obase = ((size_t)(b * T + tq0 + w) * H) + h * HD;
    o[obase + lane] = __float2half((a0 + a2) * inv);
    o[obase + lane + 32] = __float2half((a1 + a3) * inv);
}

// ---------------------------------------------------------------------------
// Orchestration
// ---------------------------------------------------------------------------
static inline void gemm(const __half* A, const __half* Wt, const float* bias,
                        const float* resid, float* Cf, __half* Ch,
                        int M, int N, int K, int gelu) {
    dim3 grid(N / 128, (M + 127) / 128);
    gemm_h_kernel<<<grid, 256>>>(A, Wt, bias, resid, Cf, Ch, M, N, K, gelu);
}
static inline void wtrans(const float* in, __half* out, int K, int N) {
    transpose_kernel<<<dim3(N / 32, K / 32), 256>>>(in, out, K, N);
}

extern "C" void kernel_launch(void* const* d_in, const int* in_sizes, int n_in,
                              void* d_out, int out_size) {
    const float* x    = (const float*)d_in[0];
    const float* ctx  = (const float*)d_in[1];
    const float* sq_w = (const float*)d_in[2];
    const float* sk_w = (const float*)d_in[3];
    const float* sv_w = (const float*)d_in[4];
    const float* so_w = (const float*)d_in[5];
    const float* so_b = (const float*)d_in[6];
    const float* cq_w = (const float*)d_in[7];
    const float* ck_w = (const float*)d_in[8];
    const float* cv_w = (const float*)d_in[9];
    const float* co_w = (const float*)d_in[10];
    const float* co_b = (const float*)d_in[11];
    const float* n1_g = (const float*)d_in[12];
    const float* n1_b = (const float*)d_in[13];
    const float* n2_g = (const float*)d_in[14];
    const float* n2_b = (const float*)d_in[15];
    const float* n3_g = (const float*)d_in[16];
    const float* n3_b = (const float*)d_in[17];
    const float* n4_g = (const float*)d_in[18];
    const float* n4_b = (const float*)d_in[19];
    const float* f1_w1 = (const float*)d_in[20];
    const float* f1_b1 = (const float*)d_in[21];
    const float* f1_w2 = (const float*)d_in[22];
    const float* f1_b2 = (const float*)d_in[23];
    const float* f2_w1 = (const float*)d_in[24];
    const float* f2_b1 = (const float*)d_in[25];
    const float* f2_w2 = (const float*)d_in[26];
    const float* f2_b2 = (const float*)d_in[27];
    float* out = (float*)d_out;

    float *px, *pq, *pk, *pv;
    __half *plnh, *pah, *phh, *pctxh, *pwt;
    cudaGetSymbolAddress((void**)&px, g_x);
    cudaGetSymbolAddress((void**)&pq, g_q);
    cudaGetSymbolAddress((void**)&pk, g_k);
    cudaGetSymbolAddress((void**)&pv, g_v);
    cudaGetSymbolAddress((void**)&plnh, g_ln_h);
    cudaGetSymbolAddress((void**)&pah, g_attn_h);
    cudaGetSymbolAddress((void**)&phh, g_hid_h);
    cudaGetSymbolAddress((void**)&pctxh, g_ctx_h);
    cudaGetSymbolAddress((void**)&pwt, g_wt);

    cudaFuncSetAttribute(attn_kernel, cudaFuncAttributeMaxDynamicSharedMemorySize,
                         ATTN_SMEM_BYTES);

    const int NTOK = BT * H;
    const int NCTX = BATCH * SC * CD;

    // seed residual stream + weight prep
    copy_kernel<<<(NTOK / 4 + 255) / 256, 256>>>((const float4*)x, (float4*)px, NTOK / 4);
    f2h_kernel<<<(NCTX + 255) / 256, 256>>>(ctx, pctxh, NCTX);
    wtrans(sq_w, pwt + WT_Q, H, H);
    wtrans(sk_w, pwt + WT_K, H, H);
    wtrans(sv_w, pwt + WT_V, H, H);
    wtrans(so_w, pwt + WT_O, H, H);
    wtrans(cq_w, pwt + WT_CQ, H, H);
    wtrans(co_w, pwt + WT_CO, H, H);
    wtrans(ck_w, pwt + WT_CK, CD, H);
    wtrans(cv_w, pwt + WT_CV, CD, H);
    wtrans(f1_w1, pwt + WT_F1A, H, FF);
    wtrans(f1_w2, pwt + WT_F1B, FF, H);
    wtrans(f2_w1, pwt + WT_F2A, H, FF);
    wtrans(f2_w2, pwt + WT_F2B, FF, H);

    // ---------------- Stage A: self-attention ----------------
    ln_kernel<<<BT, 256>>>(px, n1_g, n1_b, plnh);
    gemm(plnh, pwt + WT_Q, nullptr, nullptr, pq, nullptr, BT, H, H, 0);
    gemm(plnh, pwt + WT_K, nullptr, nullptr, pk, nullptr, BT, H, H, 0);
    gemm(plnh, pwt + WT_V, nullptr, nullptr, pv, nullptr, BT, H, H, 0);
    attn_kernel<<<dim3(T / ATQ, NH, BATCH), 256, ATTN_SMEM_BYTES>>>(pq, pk, pv, pah, T);
    gemm(pah, pwt + WT_O, so_b, px, px, nullptr, BT, H, H, 0);

    // ---------------- Stage B: FFN 1 ----------------
    ln_kernel<<<BT, 256>>>(px, n2_g, n2_b, plnh);
    gemm(plnh, pwt + WT_F1A, f1_b1, nullptr, nullptr, phh, BT, FF, H, 1);
    gemm(phh, pwt + WT_F1B, f1_b2, px, px, nullptr, BT, H, FF, 0);

    // ---------------- Stage C: cross-attention ----------------
    ln_kernel<<<BT, 256>>>(px, n3_g, n3_b, plnh);
    gemm(plnh, pwt + WT_CQ, nullptr, nullptr, pq, nullptr, BT, H, H, 0);
    gemm(pctxh, pwt + WT_CK, nullptr, nullptr, pk, nullptr, BATCH * SC, H, CD, 0);
    gemm(pctxh, pwt + WT_CV, nullptr, nullptr, pv, nullptr, BATCH * SC, H, CD, 0);
    attn_kernel<<<dim3(T / ATQ, NH, BATCH), 256, ATTN_SMEM_BYTES>>>(pq, pk, pv, pah, SC);
    gemm(pah, pwt + WT_CO, co_b, px, px, nullptr, BT, H, H, 0);

    // ---------------- Stage D: FFN 2 ----------------
    ln_kernel<<<BT, 256>>>(px, n4_g, n4_b, plnh);
    gemm(plnh, pwt + WT_F2A, f2_b1, nullptr, nullptr, phh, BT, FF, H, 1);
    gemm(phh, pwt + WT_F2B, f2_b2, px, out, nullptr, BT, H, FF, 0);
}

// round 7
// speedup vs baseline: 9.8420x; 2.6485x over previous
#include <cuda_runtime.h>
#include <cuda_fp16.h>
#include <math.h>
#include <stddef.h>
#include <stdint.h>

// ---------------------------------------------------------------------------
// Problem dims
// ---------------------------------------------------------------------------
#define BATCH 4
#define T 1024
#define H 1024
#define NH 16
#define HD 64
#define CD 768
#define SC 77
#define FF 4096
#define BT (BATCH * T)

// ---------------------------------------------------------------------------
// Scratch
// ---------------------------------------------------------------------------
__device__ float g_x[BT * H];         // residual stream (fp32)
__device__ __half g_ln_h[BT * H];     // LN output (fp16)
__device__ __half g_q_h[BT * H];
__device__ __half g_k_h[BT * H];
__device__ __half g_v_h[BT * H];
__device__ __half g_attn_h[BT * H];
__device__ __half g_hid_h[BT * FF];
__device__ __half g_ctx_h[BATCH * SC * CD];
// transposed fp16 weights, [N,K] row-major
#define WT_Q   0
#define WT_K   (WT_Q + H * H)
#define WT_V   (WT_K + H * H)
#define WT_O   (WT_V + H * H)
#define WT_CQ  (WT_O + H * H)
#define WT_CO  (WT_CQ + H * H)
#define WT_CK  (WT_CO + H * H)
#define WT_CV  (WT_CK + H * CD)
#define WT_F1A (WT_CV + H * CD)
#define WT_F1B (WT_F1A + FF * H)
#define WT_F2A (WT_F1B + H * FF)
#define WT_F2B (WT_F2A + FF * H)
#define WT_TOTAL (WT_F2B + H * FF)
__device__ __half g_wt[WT_TOTAL];

// ---------------------------------------------------------------------------
// Utility
// ---------------------------------------------------------------------------
__device__ __forceinline__ float warpSum(float v) {
#pragma unroll
    for (int o = 16; o; o >>= 1) v += __shfl_xor_sync(0xffffffffu, v, o);
    return v;
}
__device__ __forceinline__ uint32_t smem_u32(const void* p) {
    uint32_t a;
    asm("{ .reg .u64 t; cvta.to.shared.u64 t, %1; cvt.u32.u64 %0, t; }" : "=r"(a) : "l"(p));
    return a;
}
__device__ __forceinline__ void cp16(uint32_t saddr, const void* g, int srcBytes) {
    asm volatile("cp.async.cg.shared.global [%0], [%1], 16, %2;"
                 :: "r"(saddr), "l"(g), "r"(srcBytes) : "memory");
}
#define CP_COMMIT() asm volatile("cp.async.commit_group;" ::: "memory")
#define CP_WAIT1()  asm volatile("cp.async.wait_group 1;" ::: "memory")
#define CP_WAIT0()  asm volatile("cp.async.wait_group 0;" ::: "memory")

__device__ __forceinline__ void mma_f16(float* c, const uint32_t* a, const uint32_t* b) {
    asm volatile(
        "mma.sync.aligned.m16n8k16.row.col.f32.f16.f16.f32 "
        "{%0,%1,%2,%3}, {%4,%5,%6,%7}, {%8,%9}, {%0,%1,%2,%3};"
        : "+f"(c[0]), "+f"(c[1]), "+f"(c[2]), "+f"(c[3])
        : "r"(a[0]), "r"(a[1]), "r"(a[2]), "r"(a[3]), "r"(b[0]), "r"(b[1]));
}
__device__ __forceinline__ void ldm_x4(uint32_t* r, uint32_t addr) {
    asm volatile("ldmatrix.sync.aligned.m8n8.x4.shared.b16 {%0,%1,%2,%3}, [%4];"
                 : "=r"(r[0]), "=r"(r[1]), "=r"(r[2]), "=r"(r[3]) : "r"(addr));
}
__device__ __forceinline__ void ldm_x4_t(uint32_t* r, uint32_t addr) {
    asm volatile("ldmatrix.sync.aligned.m8n8.x4.trans.shared.b16 {%0,%1,%2,%3}, [%4];"
                 : "=r"(r[0]), "=r"(r[1]), "=r"(r[2]), "=r"(r[3]) : "r"(addr));
}
__device__ __forceinline__ uint32_t h2exp2(uint32_t x) {
    uint32_t r; asm("ex2.approx.f16x2 %0, %1;" : "=r"(r) : "r"(x)); return r;
}

// ---------------------------------------------------------------------------
// Small kernels
// ---------------------------------------------------------------------------
__global__ void copy_kernel(const float4* __restrict__ in, float4* __restrict__ out, int n4) {
    int i = blockIdx.x * blockDim.x + threadIdx.x;
    if (i < n4) out[i] = in[i];
}
__global__ void f2h_kernel(const float* __restrict__ in, __half* __restrict__ out, int n) {
    int i = blockIdx.x * blockDim.x + threadIdx.x;
    if (i < n) out[i] = __float2half(in[i]);
}
__global__ void transpose_kernel(const float* __restrict__ in, __half* __restrict__ out,
                                 int K, int N) {
    __shared__ float t[32][33];
    int k0 = blockIdx.y * 32, n0 = blockIdx.x * 32;
    int tx = threadIdx.x & 31, ty = threadIdx.x >> 5;
#pragma unroll
    for (int i = 0; i < 32; i += 8)
        t[ty + i][tx] = in[(size_t)(k0 + ty + i) * N + n0 + tx];
    __syncthreads();
#pragma unroll
    for (int i = 0; i < 32; i += 8)
        out[(size_t)(n0 + ty + i) * K + k0 + tx] = __float2half(t[tx][ty + i]);
}

// ---------------------------------------------------------------------------
// LayerNorm: fp32 in -> fp16 out (vectorized; 256 threads x 4 elems)
// ---------------------------------------------------------------------------
__global__ void ln_kernel(const float* __restrict__ in,
                          const float* __restrict__ gamma,
                          const float* __restrict__ beta,
                          __half* __restrict__ out) {
    int row = blockIdx.x;
    int tid = threadIdx.x;
    float4 v = ((const float4*)(in + (size_t)row * H))[tid];

    float s = v.x + v.y + v.z + v.w;
    float s2 = v.x * v.x + v.y * v.y + v.z * v.z + v.w * v.w;
    __shared__ float sh_s[8], sh_s2[8];
    float ws = warpSum(s), ws2 = warpSum(s2);
    int wid = tid >> 5, lane = tid & 31;
    if (lane == 0) { sh_s[wid] = ws; sh_s2[wid] = ws2; }
    __syncthreads();
    float tot = 0.f, tot2 = 0.f;
#pragma unroll
    for (int w = 0; w < 8; w++) { tot += sh_s[w]; tot2 += sh_s2[w]; }
    float mean = tot * (1.0f / H);
    float var = tot2 * (1.0f / H) - mean * mean;
    float inv = rsqrtf(var + 1e-5f);

    float4 gm = ((const float4*)gamma)[tid];
    float4 bt = ((const float4*)beta)[tid];
    float o0 = (v.x - mean) * inv * gm.x + bt.x;
    float o1 = (v.y - mean) * inv * gm.y + bt.y;
    float o2 = (v.z - mean) * inv * gm.z + bt.z;
    float o3 = (v.w - mean) * inv * gm.w + bt.w;
    half2 h0 = __floats2half2_rn(o0, o1);
    half2 h1 = __floats2half2_rn(o2, o3);
    ((uint2*)(out + (size_t)row * H))[tid] = make_uint2(
        *(uint32_t*)&h0, *(uint32_t*)&h1);
}

// ---------------------------------------------------------------------------
// FP16 tensor-core GEMM: C = A @ Wt^T (+bias)(+GELU)(+resid)
// ---------------------------------------------------------------------------
#define KSTR 40

__global__ __launch_bounds__(256, 2)
void gemm_h_kernel(const __half* __restrict__ A, const __half* __restrict__ Wt,
                   const float* __restrict__ bias, const float* __restrict__ resid,
                   float* __restrict__ Cf, __half* __restrict__ Ch,
                   int M, int N, int K, int do_gelu) {
    __shared__ __half sA[2][128 * KSTR];
    __shared__ __half sB[2][128 * KSTR];

    int tid = threadIdx.x;
    int lane = tid & 31, w = tid >> 5;
    int g = lane >> 2, t = lane & 3;
    int wm = w & 3, wn = w >> 2;
    int row0 = blockIdx.y * 128;
    int col0 = blockIdx.x * 128;

    uint32_t sAb[2] = { smem_u32(sA[0]), smem_u32(sA[1]) };
    uint32_t sBb[2] = { smem_u32(sB[0]), smem_u32(sB[1]) };

    int ldrow[2], ldc16[2];
#pragma unroll
    for (int i = 0; i < 2; i++) {
        int idx = i * 256 + tid;
        ldrow[i] = idx >> 2;
        ldc16[i] = idx & 3;
    }

    const int NK = K >> 5;

#pragma unroll
    for (int i = 0; i < 2; i++) {
        int r = ldrow[i], c16 = ldc16[i];
        int gr = row0 + r;
        const __half* ga = A + (size_t)(gr < M ? gr : row0) * K + c16 * 8;
        cp16(sAb[0] + (r * KSTR + c16 * 8) * 2, ga, gr < M ? 16 : 0);
        const __half* gb = Wt + (size_t)(col0 + r) * K + c16 * 8;
        cp16(sBb[0] + (r * KSTR + c16 * 8) * 2, gb, 16);
    }
    CP_COMMIT();

    float c[2][8][4];
#pragma unroll
    for (int mt = 0; mt < 2; mt++)
#pragma unroll
        for (int nt = 0; nt < 8; nt++)
#pragma unroll
            for (int i = 0; i < 4; i++) c[mt][nt][i] = 0.f;

    for (int kt = 0; kt < NK; kt++) {
        int s = kt & 1;
        if (kt + 1 < NK) {
            int sn = (kt + 1) & 1;
            int k0 = (kt + 1) << 5;
#pragma unroll
            for (int i = 0; i < 2; i++) {
                int r = ldrow[i], c16 = ldc16[i];
                int gr = row0 + r;
                const __half* ga = A + (size_t)(gr < M ? gr : row0) * K + k0 + c16 * 8;
                cp16(sAb[sn] + (r * KSTR + c16 * 8) * 2, ga, gr < M ? 16 : 0);
                const __half* gb = Wt + (size_t)(col0 + r) * K + k0 + c16 * 8;
                cp16(sBb[sn] + (r * KSTR + c16 * 8) * 2, gb, 16);
            }
        }
        CP_COMMIT();
        CP_WAIT1();
        __syncthreads();

        const __half* as = sA[s];
        const __half* bs = sB[s];
#pragma unroll
        for (int ks = 0; ks < 2; ks++) {
            int kb = ks * 16;
            uint32_t a[2][4], b[8][2];
#pragma unroll
            for (int mt = 0; mt < 2; mt++) {
                int m = wm * 32 + mt * 16 + g;
                a[mt][0] = *(const uint32_t*)(as + m * KSTR + kb + 2 * t);
                a[mt][1] = *(const uint32_t*)(as + (m + 8) * KSTR + kb + 2 * t);
                a[mt][2] = *(const uint32_t*)(as + m * KSTR + kb + 2 * t + 8);
                a[mt][3] = *(const uint32_t*)(as + (m + 8) * KSTR + kb + 2 * t + 8);
            }
#pragma unroll
            for (int nt = 0; nt < 8; nt++) {
                int n = wn * 64 + nt * 8 + g;
                b[nt][0] = *(const uint32_t*)(bs + n * KSTR + kb + 2 * t);
                b[nt][1] = *(const uint32_t*)(bs + n * KSTR + kb + 2 * t + 8);
            }
#pragma unroll
            for (int mt = 0; mt < 2; mt++)
#pragma unroll
                for (int nt = 0; nt < 8; nt++)
                    mma_f16(c[mt][nt], a[mt], b[nt]);
        }
        __syncthreads();
    }

#pragma unroll
    for (int mt = 0; mt < 2; mt++) {
        int r = row0 + wm * 32 + mt * 16 + g;
#pragma unroll
        for (int nt = 0; nt < 8; nt++) {
            int cc = col0 + wn * 64 + nt * 8 + 2 * t;
            float v0 = c[mt][nt][0], v1 = c[mt][nt][1];
            float v2 = c[mt][nt][2], v3 = c[mt][nt][3];
            if (bias) {
                float b0 = bias[cc], b1 = bias[cc + 1];
                v0 += b0; v1 += b1; v2 += b0; v3 += b1;
            }
            if (do_gelu) {
                v0 = 0.5f * v0 * (1.0f + erff(v0 * 0.70710678118654752f));
                v1 = 0.5f * v1 * (1.0f + erff(v1 * 0.70710678118654752f));
                v2 = 0.5f * v2 * (1.0f + erff(v2 * 0.70710678118654752f));
                v3 = 0.5f * v3 * (1.0f + erff(v3 * 0.70710678118654752f));
            }
            if (r < M) {
                float o0 = v0, o1 = v1;
                if (resid) { o0 += resid[(size_t)r * N + cc]; o1 += resid[(size_t)r * N + cc + 1]; }
                if (Cf) { Cf[(size_t)r * N + cc] = o0; Cf[(size_t)r * N + cc + 1] = o1; }
                if (Ch) *(half2*)(Ch + (size_t)r * N + cc) = __floats2half2_rn(o0, o1);
            }
            if (r + 8 < M) {
                float o2 = v2, o3 = v3;
                if (resid) { o2 += resid[(size_t)(r + 8) * N + cc]; o3 += resid[(size_t)(r + 8) * N + cc + 1]; }
                if (Cf) { Cf[(size_t)(r + 8) * N + cc] = o2; Cf[(size_t)(r + 8) * N + cc + 1] = o3; }
                if (Ch) *(half2*)(Ch + (size_t)(r + 8) * N + cc) = __floats2half2_rn(o2, o3);
            }
        }
    }
}

// ---------------------------------------------------------------------------
// FP16 flash attention.
//   Block: 128 threads (4 warps). 64 queries/block; warp owns 16 rows.
//   KV tiles of 64 via cp.async. Q@K^T and P@V via mma m16n8k16.
//   Online softmax in base-2, exp via ex2.approx.f16x2.
// ---------------------------------------------------------------------------
#define FA_BM 64
#define FA_BN 64
#define FSTR 72
#define SCALE_L2E 0.18033688f   // 0.125 * log2(e)

__global__ __launch_bounds__(128)
void fattn_kernel(const __half* __restrict__ Qg, const __half* __restrict__ Kg,
                  const __half* __restrict__ Vg, __half* __restrict__ Og, int Slen) {
    __shared__ __half sQ[FA_BM * FSTR];
    __shared__ __half sK[FA_BN * FSTR];
    __shared__ __half sV[FA_BN * FSTR];

    int b = blockIdx.z, h = blockIdx.y;
    int q0 = blockIdx.x * FA_BM;
    int tid = threadIdx.x, w = tid >> 5, lane = tid & 31;
    int g = lane >> 2, t = lane & 3;

    uint32_t sQb = smem_u32(sQ), sKb = smem_u32(sK), sVb = smem_u32(sV);

    // load Q tile (64 x 64)
#pragma unroll
    for (int i = 0; i < 4; i++) {
        int idx = i * 128 + tid;
        int r = idx >> 3, c = (idx & 7) * 8;
        const __half* gp = Qg + ((size_t)(b * T + q0 + r) * H) + h * HD + c;
        cp16(sQb + (r * FSTR + c) * 2, gp, 16);
    }
    CP_COMMIT();
    CP_WAIT0();
    __syncthreads();

    // Q a-frags (fixed for whole kernel): rows w*16..w*16+15, 4 k-steps
    uint32_t aq[4][4];
    {
        int row = w * 16 + (lane & 7) + ((lane & 8) ? 8 : 0);
#pragma unroll
        for (int kt = 0; kt < 4; kt++) {
            int col = kt * 16 + ((lane & 16) ? 8 : 0);
            ldm_x4(aq[kt], sQb + (row * FSTR + col) * 2);
        }
    }

    float m0 = -1e30f, m1 = -1e30f, l0 = 0.f, l1 = 0.f;
    float o[8][4];
#pragma unroll
    for (int dt = 0; dt < 8; dt++)
#pragma unroll
        for (int i = 0; i < 4; i++) o[dt][i] = 0.f;

    for (int j0 = 0; j0 < Slen; j0 += FA_BN) {
        __syncthreads();
        // load K,V tiles
#pragma unroll
        for (int i = 0; i < 4; i++) {
            int idx = i * 128 + tid;
            int r = idx >> 3, c = (idx & 7) * 8;
            int j = j0 + r;
            int ok = (j < Slen) ? 16 : 0;
            size_t goff = ((size_t)(b * Slen + (j < Slen ? j : 0)) * H) + h * HD + c;
            cp16(sKb + (r * FSTR + c) * 2, Kg + goff, ok);
            cp16(sVb + (r * FSTR + c) * 2, Vg + goff, ok);
        }
        CP_COMMIT();
        CP_WAIT0();
        __syncthreads();

        // ---- scores: S = Q @ K^T (warp tile 16 x 64)
        float c[8][4];
#pragma unroll
        for (int nt = 0; nt < 8; nt++)
#pragma unroll
            for (int i = 0; i < 4; i++) c[nt][i] = 0.f;

        {
            int krow = (lane & 7) + ((lane & 16) ? 8 : 0);
            int kcol = (lane & 8) ? 8 : 0;
#pragma unroll
            for (int kt = 0; kt < 4; kt++) {
#pragma unroll
                for (int nt2 = 0; nt2 < 4; nt2++) {
                    uint32_t bb[4];
                    ldm_x4(bb, sKb + ((nt2 * 16 + krow) * FSTR + kt * 16 + kcol) * 2);
                    mma_f16(c[nt2 * 2], aq[kt], bb);
                    mma_f16(c[nt2 * 2 + 1], aq[kt], bb + 2);
                }
            }
        }

        // scale to base-2 + mask
#pragma unroll
        for (int nt = 0; nt < 8; nt++)
#pragma unroll
            for (int i = 0; i < 4; i++) c[nt][i] *= SCALE_L2E;
        if (j0 + FA_BN > Slen) {
#pragma unroll
            for (int nt = 0; nt < 8; nt++) {
                int ja = j0 + nt * 8 + 2 * t;
                if (ja >= Slen) { c[nt][0] = -1e30f; c[nt][2] = -1e30f; }
                if (ja + 1 >= Slen) { c[nt][1] = -1e30f; c[nt][3] = -1e30f; }
            }
        }

        // tile row max (reduce across the 4 t-lanes)
        float tm0 = -1e30f, tm1 = -1e30f;
#pragma unroll
        for (int nt = 0; nt < 8; nt++) {
            tm0 = fmaxf(tm0, fmaxf(c[nt][0], c[nt][1]));
            tm1 = fmaxf(tm1, fmaxf(c[nt][2], c[nt][3]));
        }
        tm0 = fmaxf(tm0, __shfl_xor_sync(0xffffffffu, tm0, 1));
        tm0 = fmaxf(tm0, __shfl_xor_sync(0xffffffffu, tm0, 2));
        tm1 = fmaxf(tm1, __shfl_xor_sync(0xffffffffu, tm1, 1));
        tm1 = fmaxf(tm1, __shfl_xor_sync(0xffffffffu, tm1, 2));

        float mn0 = fmaxf(m0, tm0), mn1 = fmaxf(m1, tm1);
        float al0 = exp2f(m0 - mn0), al1 = exp2f(m1 - mn1);
        m0 = mn0; m1 = mn1;

        // P = 2^(x - m), fp16 pairs; row sums
        uint32_t ph[8][2];
        float s0 = 0.f, s1 = 0.f;
#pragma unroll
        for (int nt = 0; nt < 8; nt++) {
            half2 x0 = __floats2half2_rn(c[nt][0] - mn0, c[nt][1] - mn0);
            half2 x1 = __floats2half2_rn(c[nt][2] - mn1, c[nt][3] - mn1);
            ph[nt][0] = h2exp2(*(uint32_t*)&x0);
            ph[nt][1] = h2exp2(*(uint32_t*)&x1);
            float2 f0 = __half22float2(*(half2*)&ph[nt][0]);
            float2 f1 = __half22float2(*(half2*)&ph[nt][1]);
            s0 += f0.x + f0.y;
            s1 += f1.x + f1.y;
        }
        // BUGFIX (R6): reduce row sums across the 4 t-lanes; each lane only
        // holds 16 of the 64 tile columns.
        s0 += __shfl_xor_sync(0xffffffffu, s0, 1);
        s0 += __shfl_xor_sync(0xffffffffu, s0, 2);
        s1 += __shfl_xor_sync(0xffffffffu, s1, 1);
        s1 += __shfl_xor_sync(0xffffffffu, s1, 2);
        l0 = l0 * al0 + s0;
        l1 = l1 * al1 + s1;

        // rescale O
#pragma unroll
        for (int dt = 0; dt < 8; dt++) {
            o[dt][0] *= al0; o[dt][1] *= al0;
            o[dt][2] *= al1; o[dt][3] *= al1;
        }

        // ---- O += P @ V
        {
            int vrow = (lane & 7) + ((lane & 8) ? 8 : 0);
            int vcol = (lane & 16) ? 8 : 0;
#pragma unroll
            for (int kt = 0; kt < 4; kt++) {
                uint32_t af[4] = { ph[2 * kt][0], ph[2 * kt][1],
                                   ph[2 * kt + 1][0], ph[2 * kt + 1][1] };
#pragma unroll
                for (int dt2 = 0; dt2 < 4; dt2++) {
                    uint32_t bb[4];
                    ldm_x4_t(bb, sVb + ((kt * 16 + vrow) * FSTR + dt2 * 16 + vcol) * 2);
                    mma_f16(o[dt2 * 2], af, bb);
                    mma_f16(o[dt2 * 2 + 1], af, bb + 2);
                }
            }
        }
    }

    // epilogue
    float inv0 = 1.0f / l0, inv1 = 1.0f / l1;
    int row0 = q0 + w * 16 + g;
#pragma unroll
    for (int dt = 0; dt < 8; dt++) {
        int col = dt * 8 + 2 * t;
        half2 h0 = __floats2half2_rn(o[dt][0] * inv0, o[dt][1] * inv0);
        half2 h1 = __floats2half2_rn(o[dt][2] * inv1, o[dt][3] * inv1);
        *(half2*)(Og + ((size_t)(b * T + row0) * H) + h * HD + col) = h0;
        *(half2*)(Og + ((size_t)(b * T + row0 + 8) * H) + h * HD + col) = h1;
    }
}

// ---------------------------------------------------------------------------
// Orchestration
// ---------------------------------------------------------------------------
static inline void gemm(const __half* A, const __half* Wt, const float* bias,
                        const float* resid, float* Cf, __half* Ch,
                        int M, int N, int K, int gelu) {
    dim3 grid(N / 128, (M + 127) / 128);
    gemm_h_kernel<<<grid, 256>>>(A, Wt, bias, resid, Cf, Ch, M, N, K, gelu);
}
static inline void wtrans(const float* in, __half* out, int K, int N) {
    transpose_kernel<<<dim3(N / 32, K / 32), 256>>>(in, out, K, N);
}

extern "C" void kernel_launch(void* const* d_in, const int* in_sizes, int n_in,
                              void* d_out, int out_size) {
    const float* x    = (const float*)d_in[0];
    const float* ctx  = (const float*)d_in[1];
    const float* sq_w = (const float*)d_in[2];
    const float* sk_w = (const float*)d_in[3];
    const float* sv_w = (const float*)d_in[4];
    const float* so_w = (const float*)d_in[5];
    const float* so_b = (const float*)d_in[6];
    const float* cq_w = (const float*)d_in[7];
    const float* ck_w = (const float*)d_in[8];
    const float* cv_w = (const float*)d_in[9];
    const float* co_w = (const float*)d_in[10];
    const float* co_b = (const float*)d_in[11];
    const float* n1_g = (const float*)d_in[12];
    const float* n1_b = (const float*)d_in[13];
    const float* n2_g = (const float*)d_in[14];
    const float* n2_b = (const float*)d_in[15];
    const float* n3_g = (const float*)d_in[16];
    const float* n3_b = (const float*)d_in[17];
    const float* n4_g = (const float*)d_in[18];
    const float* n4_b = (const float*)d_in[19];
    const float* f1_w1 = (const float*)d_in[20];
    const float* f1_b1 = (const float*)d_in[21];
    const float* f1_w2 = (const float*)d_in[22];
    const float* f1_b2 = (const float*)d_in[23];
    const float* f2_w1 = (const float*)d_in[24];
    const float* f2_b1 = (const float*)d_in[25];
    const float* f2_w2 = (const float*)d_in[26];
    const float* f2_b2 = (const float*)d_in[27];
    float* out = (float*)d_out;

    float* px;
    __half *plnh, *pqh, *pkh, *pvh, *pah, *phh, *pctxh, *pwt;
    cudaGetSymbolAddress((void**)&px, g_x);
    cudaGetSymbolAddress((void**)&plnh, g_ln_h);
    cudaGetSymbolAddress((void**)&pqh, g_q_h);
    cudaGetSymbolAddress((void**)&pkh, g_k_h);
    cudaGetSymbolAddress((void**)&pvh, g_v_h);
    cudaGetSymbolAddress((void**)&pah, g_attn_h);
    cudaGetSymbolAddress((void**)&phh, g_hid_h);
    cudaGetSymbolAddress((void**)&pctxh, g_ctx_h);
    cudaGetSymbolAddress((void**)&pwt, g_wt);

    const int NTOK = BT * H;
    const int NCTX = BATCH * SC * CD;

    copy_kernel<<<(NTOK / 4 + 255) / 256, 256>>>((const float4*)x, (float4*)px, NTOK / 4);
    f2h_kernel<<<(NCTX + 255) / 256, 256>>>(ctx, pctxh, NCTX);
    wtrans(sq_w, pwt + WT_Q, H, H);
    wtrans(sk_w, pwt + WT_K, H, H);
    wtrans(sv_w, pwt + WT_V, H, H);
    wtrans(so_w, pwt + WT_O, H, H);
    wtrans(cq_w, pwt + WT_CQ, H, H);
    wtrans(co_w, pwt + WT_CO, H, H);
    wtrans(ck_w, pwt + WT_CK, CD, H);
    wtrans(cv_w, pwt + WT_CV, CD, H);
    wtrans(f1_w1, pwt + WT_F1A, H, FF);
    wtrans(f1_w2, pwt + WT_F1B, FF, H);
    wtrans(f2_w1, pwt + WT_F2A, H, FF);
    wtrans(f2_w2, pwt + WT_F2B, FF, H);

    // ---------------- Stage A: self-attention ----------------
    ln_kernel<<<BT, 256>>>(px, n1_g, n1_b, plnh);
    gemm(plnh, pwt + WT_Q, nullptr, nullptr, nullptr, pqh, BT, H, H, 0);
    gemm(plnh, pwt + WT_K, nullptr, nullptr, nullptr, pkh, BT, H, H, 0);
    gemm(plnh, pwt + WT_V, nullptr, nullptr, nullptr, pvh, BT, H, H, 0);
    fattn_kernel<<<dim3(T / FA_BM, NH, BATCH), 128>>>(pqh, pkh, pvh, pah, T);
    gemm(pah, pwt + WT_O, so_b, px, px, nullptr, BT, H, H, 0);

    // ---------------- Stage B: FFN 1 ----------------
    ln_kernel<<<BT, 256>>>(px, n2_g, n2_b, plnh);
    gemm(plnh, pwt + WT_F1A, f1_b1, nullptr, nullptr, phh, BT, FF, H, 1);
    gemm(phh, pwt + WT_F1B, f1_b2, px, px, nullptr, BT, H, FF, 0);

    // ---------------- Stage C: cross-attention ----------------
    ln_kernel<<<BT, 256>>>(px, n3_g, n3_b, plnh);
    gemm(plnh, pwt + WT_CQ, nullptr, nullptr, nullptr, pqh, BT, H, H, 0);
    gemm(pctxh, pwt + WT_CK, nullptr, nullptr, nullptr, pkh, BATCH * SC, H, CD, 0);
    gemm(pctxh, pwt + WT_CV, nullptr, nullptr, nullptr, pvh, BATCH * SC, H, CD, 0);
    fattn_kernel<<<dim3(T / FA_BM, NH, BATCH), 128>>>(pqh, pkh, pvh, pah, SC);
    gemm(pah, pwt + WT_CO, co_b, px, px, nullptr, BT, H, H, 0);

    // ---------------- Stage D: FFN 2 ----------------
    ln_kernel<<<BT, 256>>>(px, n4_g, n4_b, plnh);
    gemm(plnh, pwt + WT_F2A, f2_b1, nullptr, nullptr, phh, BT, FF, H, 1);
    gemm(phh, pwt + WT_F2B, f2_b2, px, out, nullptr, BT, H, FF, 0);
}